// round 2
// baseline (speedup 1.0000x reference)
#include <cuda_runtime.h>
#include <math.h>

// Problem constants
#define BB 4
#define NN 512
#define MM 4096
#define DD 256
#define HH 8
// HD = 32, scale = 1/sqrt(32)
#define SCALE 0.17677669529663687f

// Scratch (static device globals: allowed; no runtime allocation)
__device__ float g_amr_qk [BB*NN*DD];
__device__ float g_amr_v  [BB*NN*DD];
__device__ float g_vis_qk [BB*MM*DD];
__device__ float g_vis_v  [BB*MM*DD];
__device__ float g_amr_att[BB*NN*DD];
__device__ float g_vis_att[BB*MM*DD];

// ----------------------------------------------------------------------------
// Tiled fp32 GEMM: C[S,256] = A[S,256] @ W[256,256]
// Block tile 64x64, 256 threads, 4x4 per-thread microtile, k-chunk 16.
// EPI=true: C = (A@W + bias[col]) * Xm   (fused output projection + gate)
// Grid: (4 col tiles, S/64 row tiles). S is always a multiple of 64.
// ----------------------------------------------------------------------------
template <bool EPI>
__global__ void __launch_bounds__(256) gemm256(const float* __restrict__ A,
                                               const float* __restrict__ W,
                                               const float* __restrict__ bias,
                                               const float* __restrict__ Xm,
                                               float* __restrict__ C)
{
    __shared__ float As[64][16];
    __shared__ float Ws[16][64];

    const int row0 = blockIdx.y * 64;
    const int col0 = blockIdx.x * 64;
    const int tid  = threadIdx.x;
    const int ty   = tid >> 4;        // 0..15  (row group)
    const int tx   = tid & 15;        // 0..15  (col group)
    const int ar   = tid >> 2;        // 0..63  (A-tile load row)
    const int ac   = (tid & 3) * 4;   // 0,4,8,12

    float acc[4][4];
    #pragma unroll
    for (int i = 0; i < 4; i++)
        #pragma unroll
        for (int j = 0; j < 4; j++) acc[i][j] = 0.0f;

    for (int kc = 0; kc < 256; kc += 16) {
        // Stage A tile: 64 rows x 16 k-cols (one float4 per thread)
        *(float4*)&As[ar][ac] =
            *(const float4*)&A[(size_t)(row0 + ar) * 256 + kc + ac];
        // Stage W tile: 16 k-rows x 64 cols (one float4 per thread)
        *(float4*)&Ws[ty][tx * 4] =
            *(const float4*)&W[(size_t)(kc + ty) * 256 + col0 + tx * 4];
        __syncthreads();

        #pragma unroll
        for (int k = 0; k < 16; k++) {
            const float a0 = As[ty * 4 + 0][k];
            const float a1 = As[ty * 4 + 1][k];
            const float a2 = As[ty * 4 + 2][k];
            const float a3 = As[ty * 4 + 3][k];
            const float4 b = *(const float4*)&Ws[k][tx * 4];
            acc[0][0] += a0 * b.x; acc[0][1] += a0 * b.y;
            acc[0][2] += a0 * b.z; acc[0][3] += a0 * b.w;
            acc[1][0] += a1 * b.x; acc[1][1] += a1 * b.y;
            acc[1][2] += a1 * b.z; acc[1][3] += a1 * b.w;
            acc[2][0] += a2 * b.x; acc[2][1] += a2 * b.y;
            acc[2][2] += a2 * b.z; acc[2][3] += a2 * b.w;
            acc[3][0] += a3 * b.x; acc[3][1] += a3 * b.y;
            acc[3][2] += a3 * b.z; acc[3][3] += a3 * b.w;
        }
        __syncthreads();
    }

    const int c0 = col0 + tx * 4;
    #pragma unroll
    for (int i = 0; i < 4; i++) {
        const size_t r = (size_t)(row0 + ty * 4 + i);
        float4 v;
        v.x = acc[i][0]; v.y = acc[i][1]; v.z = acc[i][2]; v.w = acc[i][3];
        if (EPI) {
            const float4 bv = *(const float4*)&bias[c0];
            const float4 xv = *(const float4*)&Xm[r * 256 + c0];
            v.x = (v.x + bv.x) * xv.x;
            v.y = (v.y + bv.y) * xv.y;
            v.z = (v.z + bv.z) * xv.z;
            v.w = (v.w + bv.w) * xv.w;
        }
        *(float4*)&C[r * 256 + c0] = v;
    }
}

// ----------------------------------------------------------------------------
// Flash-style cross attention, fp32, online softmax.
// Q/K/V stored merged as [b, s, 256]; head h = cols [32h, 32h+32).
// One thread per query row; 64 queries per block; key chunks of 64.
// mask != nullptr: key n with mask[b*Lk+n] != 0 gets score -3e38 (softmax -> 0).
// Output written merged-heads: Op[(b*Lq+q)*256 + h*32 + c].
// Grid: (Lq/64, H, B), block 64.
// ----------------------------------------------------------------------------
__global__ void __launch_bounds__(64) attn64(const float* __restrict__ Qp,
                                             const float* __restrict__ Kp,
                                             const float* __restrict__ Vp,
                                             float* __restrict__ Op,
                                             const int* __restrict__ mask,
                                             int Lq, int Lk)
{
    __shared__ float Ks[64][32];
    __shared__ float Vs[64][32];

    const int b = blockIdx.z;
    const int h = blockIdx.y;
    const int t = threadIdx.x;                 // 0..63
    const int q = blockIdx.x * 64 + t;

    // Load this thread's query row (32 floats) into registers
    float qr[32];
    const float* qptr = &Qp[((size_t)b * Lq + q) * 256 + h * 32];
    #pragma unroll
    for (int c = 0; c < 32; c += 4) {
        const float4 v = *(const float4*)&qptr[c];
        qr[c] = v.x; qr[c + 1] = v.y; qr[c + 2] = v.z; qr[c + 3] = v.w;
    }

    float o[32];
    #pragma unroll
    for (int c = 0; c < 32; c++) o[c] = 0.0f;
    float m_run = -1e30f;
    float l_run = 0.0f;

    for (int kc = 0; kc < Lk; kc += 64) {
        // Cooperative stage: thread t loads K/V row (kc+t), 8 float4 each
        {
            const size_t base = ((size_t)b * Lk + kc + t) * 256 + h * 32;
            #pragma unroll
            for (int c = 0; c < 32; c += 4) {
                *(float4*)&Ks[t][c] = *(const float4*)&Kp[base + c];
                *(float4*)&Vs[t][c] = *(const float4*)&Vp[base + c];
            }
        }
        __syncthreads();

        #pragma unroll 1
        for (int j0 = 0; j0 < 64; j0 += 16) {
            float s[16];
            float cmax = -1e30f;
            #pragma unroll
            for (int j = 0; j < 16; j++) {
                float acc = 0.0f;
                #pragma unroll
                for (int c = 0; c < 32; c += 4) {
                    const float4 kv = *(const float4*)&Ks[j0 + j][c];
                    acc += qr[c]     * kv.x;
                    acc += qr[c + 1] * kv.y;
                    acc += qr[c + 2] * kv.z;
                    acc += qr[c + 3] * kv.w;
                }
                acc *= SCALE;
                if (mask && mask[b * Lk + kc + j0 + j]) acc = -3.0e38f;
                s[j] = acc;
                cmax = fmaxf(cmax, acc);
            }
            const float m_new = fmaxf(m_run, cmax);
            const float alpha = __expf(m_run - m_new);
            l_run *= alpha;
            #pragma unroll
            for (int c = 0; c < 32; c++) o[c] *= alpha;
            #pragma unroll
            for (int j = 0; j < 16; j++) {
                const float p = __expf(s[j] - m_new);
                l_run += p;
                #pragma unroll
                for (int c = 0; c < 32; c += 4) {
                    const float4 vv = *(const float4*)&Vs[j0 + j][c];
                    o[c]     += p * vv.x;
                    o[c + 1] += p * vv.y;
                    o[c + 2] += p * vv.z;
                    o[c + 3] += p * vv.w;
                }
            }
            m_run = m_new;
        }
        __syncthreads();
    }

    const float inv = 1.0f / l_run;
    float* optr = &Op[((size_t)b * Lq + q) * 256 + h * 32];
    #pragma unroll
    for (int c = 0; c < 32; c += 4) {
        float4 v;
        v.x = o[c] * inv; v.y = o[c + 1] * inv;
        v.z = o[c + 2] * inv; v.w = o[c + 3] * inv;
        *(float4*)&optr[c] = v;
    }
}

// ----------------------------------------------------------------------------
extern "C" void kernel_launch(void* const* d_in, const int* in_sizes, int n_in,
                              void* d_out, int out_size)
{
    const float* amr      = (const float*)d_in[0];
    const int*   pad_mask = (const int*)  d_in[1];   // bool -> int32 (assumed)
    const float* vis      = (const float*)d_in[2];
    const float* W_amr_qk = (const float*)d_in[3];
    const float* W_amr_v  = (const float*)d_in[4];
    const float* W_vis_qk = (const float*)d_in[5];
    const float* W_vis_v  = (const float*)d_in[6];
    const float* W_amr_out= (const float*)d_in[7];
    const float* b_amr_out= (const float*)d_in[8];
    const float* W_vis_out= (const float*)d_in[9];
    const float* b_vis_out= (const float*)d_in[10];

    float* out_amr = (float*)d_out;                       // [4,512,256]
    float* out_vis = out_amr + (size_t)BB * NN * DD;      // [4,4096,256]

    float *amr_qk, *amr_v, *vis_qk, *vis_v, *amr_att, *vis_att;
    cudaGetSymbolAddress((void**)&amr_qk,  g_amr_qk);
    cudaGetSymbolAddress((void**)&amr_v,   g_amr_v);
    cudaGetSymbolAddress((void**)&vis_qk,  g_vis_qk);
    cudaGetSymbolAddress((void**)&vis_v,   g_vis_v);
    cudaGetSymbolAddress((void**)&amr_att, g_amr_att);
    cudaGetSymbolAddress((void**)&vis_att, g_vis_att);

    const dim3 gA(4, (BB * NN) / 64);   // amr-side GEMMs: 2048 rows
    const dim3 gV(4, (BB * MM) / 64);   // vis-side GEMMs: 16384 rows

    // Projections
    gemm256<false><<<gA, 256>>>(amr, W_amr_qk, nullptr, nullptr, amr_qk);
    gemm256<false><<<gA, 256>>>(amr, W_amr_v,  nullptr, nullptr, amr_v);
    gemm256<false><<<gV, 256>>>(vis, W_vis_qk, nullptr, nullptr, vis_qk);
    gemm256<false><<<gV, 256>>>(vis, W_vis_v,  nullptr, nullptr, vis_v);

    // Direction 1: amr -> visual (no mask), softmax over M
    attn64<<<dim3(NN / 64, HH, BB), 64>>>(amr_qk, vis_qk, vis_v, amr_att,
                                          nullptr, NN, MM);
    // Direction 2: visual -> amr (key mask = amr_pad_mask), softmax over N
    attn64<<<dim3(MM / 64, HH, BB), 64>>>(vis_qk, amr_qk, amr_v, vis_att,
                                          pad_mask, MM, NN);

    // Output projections with fused bias + elementwise gate
    gemm256<true><<<gA, 256>>>(amr_att, W_amr_out, b_amr_out, amr, out_amr);
    gemm256<true><<<gV, 256>>>(vis_att, W_vis_out, b_vis_out, vis, out_vis);
}

// round 5
// speedup vs baseline: 2.3913x; 2.3913x over previous
#include <cuda_runtime.h>
#include <math.h>
#include <stdint.h>

// Problem constants
#define BB 4
#define NN 512
#define MM 4096
#define DD 256
#define HH 8
// HD = 32, scale = 1/sqrt(32)
#define SCALE 0.17677669529663687f

// Scratch (static device globals)
__device__ float g_amr_qk [BB*NN*DD];
__device__ float g_amr_v  [BB*NN*DD];
__device__ float g_vis_qk [BB*MM*DD];
__device__ float g_vis_v  [BB*MM*DD];
__device__ float g_amr_att[BB*NN*DD];
__device__ float g_vis_att[BB*MM*DD];

// ---------------------------------------------------------------------------
// tf32 helpers
// ---------------------------------------------------------------------------
__device__ __forceinline__ float f2tf32f(float f) {
    uint32_t r;
    asm("cvt.rna.tf32.f32 %0, %1;" : "=r"(r) : "f"(f));
    return __uint_as_float(r);
}

__device__ __forceinline__ void mma_tf32(float c[4],
                                         uint32_t a0, uint32_t a1,
                                         uint32_t a2, uint32_t a3,
                                         uint32_t b0, uint32_t b1) {
    asm volatile(
        "mma.sync.aligned.m16n8k8.row.col.f32.tf32.tf32.f32 "
        "{%0,%1,%2,%3}, {%4,%5,%6,%7}, {%8,%9}, {%0,%1,%2,%3};"
        : "+f"(c[0]), "+f"(c[1]), "+f"(c[2]), "+f"(c[3])
        : "r"(a0), "r"(a1), "r"(a2), "r"(a3), "r"(b0), "r"(b1));
}

// ---------------------------------------------------------------------------
// tf32 tensor-core GEMM: C[S,256] = A[S,256] @ W[256,256]
// Block: 128 threads (4 warps), tile 64x64. Warp w owns rows [16w,16w+16).
// K chunk = 32 (4 k-steps of 8). EPI: C = (A@W + bias[col]) * Xm.
// Grid: (4 col tiles, S/64 row tiles).
// ---------------------------------------------------------------------------
template <bool EPI>
__global__ void __launch_bounds__(128) gemm_mma(const float* __restrict__ A,
                                                const float* __restrict__ W,
                                                const float* __restrict__ bias,
                                                const float* __restrict__ Xm,
                                                float* __restrict__ C)
{
    __shared__ float As[64][36];   // 64 rows x 32 k (pad 36: bank = 4g+t)
    __shared__ float Ws[32][72];   // 32 k-rows x 64 cols (pad 72: bank = 8t+g)

    const int row0 = blockIdx.y * 64;
    const int col0 = blockIdx.x * 64;
    const int tid  = threadIdx.x;
    const int w    = tid >> 5;
    const int lane = tid & 31;
    const int g    = lane >> 2;    // groupID 0..7
    const int t    = lane & 3;     // thread-in-group 0..3

    float acc[8][4];
    #pragma unroll
    for (int nt = 0; nt < 8; nt++)
        #pragma unroll
        for (int i = 0; i < 4; i++) acc[nt][i] = 0.0f;

    for (int kc = 0; kc < 256; kc += 32) {
        __syncthreads();
        // Stage A chunk: 64 x 32 floats (tf32-rounded)
        for (int i = tid; i < 512; i += 128) {
            const int r  = i >> 3;
            const int c4 = (i & 7) * 4;
            const float4 v = *(const float4*)&A[(size_t)(row0 + r) * 256 + kc + c4];
            As[r][c4 + 0] = f2tf32f(v.x);
            As[r][c4 + 1] = f2tf32f(v.y);
            As[r][c4 + 2] = f2tf32f(v.z);
            As[r][c4 + 3] = f2tf32f(v.w);
        }
        // Stage W chunk: 32 k-rows x 64 cols
        for (int i = tid; i < 512; i += 128) {
            const int r  = i >> 4;
            const int c4 = (i & 15) * 4;
            const float4 v = *(const float4*)&W[(size_t)(kc + r) * 256 + col0 + c4];
            Ws[r][c4 + 0] = f2tf32f(v.x);
            Ws[r][c4 + 1] = f2tf32f(v.y);
            Ws[r][c4 + 2] = f2tf32f(v.z);
            Ws[r][c4 + 3] = f2tf32f(v.w);
        }
        __syncthreads();

        #pragma unroll
        for (int kk = 0; kk < 4; kk++) {
            const int k8 = kk * 8;
            const uint32_t a0 = __float_as_uint(As[16 * w + g    ][k8 + t    ]);
            const uint32_t a1 = __float_as_uint(As[16 * w + g + 8][k8 + t    ]);
            const uint32_t a2 = __float_as_uint(As[16 * w + g    ][k8 + t + 4]);
            const uint32_t a3 = __float_as_uint(As[16 * w + g + 8][k8 + t + 4]);
            #pragma unroll
            for (int nt = 0; nt < 8; nt++) {
                const uint32_t b0 = __float_as_uint(Ws[k8 + t    ][nt * 8 + g]);
                const uint32_t b1 = __float_as_uint(Ws[k8 + t + 4][nt * 8 + g]);
                mma_tf32(acc[nt], a0, a1, a2, a3, b0, b1);
            }
        }
    }

    // Epilogue: rows (row0+16w+g) and (+8); per n-tile cols col0+nt*8+{2t,2t+1}
    const size_t r_lo = (size_t)(row0 + 16 * w + g);
    const size_t r_hi = r_lo + 8;
    #pragma unroll
    for (int nt = 0; nt < 8; nt++) {
        const int col = col0 + nt * 8 + 2 * t;
        float2 lo = make_float2(acc[nt][0], acc[nt][1]);
        float2 hi = make_float2(acc[nt][2], acc[nt][3]);
        if (EPI) {
            const float2 bv  = *(const float2*)&bias[col];
            const float2 xlo = *(const float2*)&Xm[r_lo * 256 + col];
            const float2 xhi = *(const float2*)&Xm[r_hi * 256 + col];
            lo.x = (lo.x + bv.x) * xlo.x; lo.y = (lo.y + bv.y) * xlo.y;
            hi.x = (hi.x + bv.x) * xhi.x; hi.y = (hi.y + bv.y) * xhi.y;
        }
        *(float2*)&C[r_lo * 256 + col] = lo;
        *(float2*)&C[r_hi * 256 + col] = hi;
    }
}

// ---------------------------------------------------------------------------
// Flash cross-attention with tf32 mma.sync.
// 128 threads / 4 warps; 64 queries per block; 64-key chunks.
// Warp w owns query rows [16w, 16w+16). Q frags register-resident, scaled.
// mask != nullptr: key j with mask[b*Lk+j] != 0 scored -3e38.
// Grid: (Lq/64, H, B).
// ---------------------------------------------------------------------------
__global__ void __launch_bounds__(128) attn_mma(const float* __restrict__ Qp,
                                                const float* __restrict__ Kp,
                                                const float* __restrict__ Vp,
                                                float* __restrict__ Op,
                                                const int* __restrict__ mask,
                                                int Lq, int Lk)
{
    __shared__ float Qs[64][36];   // bank = 4g+t for frag loads
    __shared__ float Ks[64][36];
    __shared__ float Vs[64][40];   // bank = 8t+g for B-frag loads
    __shared__ int   Msk[64];

    const int b  = blockIdx.z;
    const int h  = blockIdx.y;
    const int q0 = blockIdx.x * 64;
    const int tid  = threadIdx.x;
    const int w    = tid >> 5;
    const int lane = tid & 31;
    const int g    = lane >> 2;
    const int t    = lane & 3;

    // Stage Q tile (scaled + tf32)
    for (int i = tid; i < 512; i += 128) {
        const int r  = i >> 3;
        const int c4 = (i & 7) * 4;
        const float4 v = *(const float4*)&Qp[((size_t)b * Lq + q0 + r) * 256 + h * 32 + c4];
        Qs[r][c4 + 0] = f2tf32f(v.x * SCALE);
        Qs[r][c4 + 1] = f2tf32f(v.y * SCALE);
        Qs[r][c4 + 2] = f2tf32f(v.z * SCALE);
        Qs[r][c4 + 3] = f2tf32f(v.w * SCALE);
    }
    __syncthreads();

    // Q fragments: qa[kk][0..3] for k-steps kk*8
    uint32_t qa[4][4];
    #pragma unroll
    for (int kk = 0; kk < 4; kk++) {
        const int k8 = kk * 8;
        qa[kk][0] = __float_as_uint(Qs[16 * w + g    ][k8 + t    ]);
        qa[kk][1] = __float_as_uint(Qs[16 * w + g + 8][k8 + t    ]);
        qa[kk][2] = __float_as_uint(Qs[16 * w + g    ][k8 + t + 4]);
        qa[kk][3] = __float_as_uint(Qs[16 * w + g + 8][k8 + t + 4]);
    }

    // O fragments (16 rows x 32 HD per warp): of[nt][0..3]
    float of[4][4];
    #pragma unroll
    for (int nt = 0; nt < 4; nt++)
        #pragma unroll
        for (int i = 0; i < 4; i++) of[nt][i] = 0.0f;

    float m_lo = -1e30f, m_hi = -1e30f, l_lo = 0.0f, l_hi = 0.0f;

    for (int kc = 0; kc < Lk; kc += 64) {
        __syncthreads();   // previous chunk's reads of Ks/Vs complete
        // Stage K/V chunk (tf32) + mask
        for (int i = tid; i < 512; i += 128) {
            const int r  = i >> 3;
            const int c4 = (i & 7) * 4;
            const size_t base = ((size_t)b * Lk + kc + r) * 256 + h * 32 + c4;
            const float4 kv = *(const float4*)&Kp[base];
            const float4 vv = *(const float4*)&Vp[base];
            Ks[r][c4 + 0] = f2tf32f(kv.x); Ks[r][c4 + 1] = f2tf32f(kv.y);
            Ks[r][c4 + 2] = f2tf32f(kv.z); Ks[r][c4 + 3] = f2tf32f(kv.w);
            Vs[r][c4 + 0] = f2tf32f(vv.x); Vs[r][c4 + 1] = f2tf32f(vv.y);
            Vs[r][c4 + 2] = f2tf32f(vv.z); Vs[r][c4 + 3] = f2tf32f(vv.w);
        }
        if (mask) {
            for (int i = tid; i < 64; i += 128) Msk[i] = mask[b * Lk + kc + i];
        }
        __syncthreads();

        // ---- Scores: S (16 x 64 per warp) = Q K^T ----
        float sf[8][4];
        #pragma unroll
        for (int nt = 0; nt < 8; nt++) {
            sf[nt][0] = 0.0f; sf[nt][1] = 0.0f; sf[nt][2] = 0.0f; sf[nt][3] = 0.0f;
            #pragma unroll
            for (int kk = 0; kk < 4; kk++) {
                const int k8 = kk * 8;
                const uint32_t b0 = __float_as_uint(Ks[nt * 8 + g][k8 + t    ]);
                const uint32_t b1 = __float_as_uint(Ks[nt * 8 + g][k8 + t + 4]);
                mma_tf32(sf[nt], qa[kk][0], qa[kk][1], qa[kk][2], qa[kk][3], b0, b1);
            }
        }

        // ---- Mask fixup (per key column) ----
        if (mask) {
            #pragma unroll
            for (int nt = 0; nt < 8; nt++) {
                const int c = nt * 8 + 2 * t;
                if (Msk[c    ]) { sf[nt][0] = -3.0e38f; sf[nt][2] = -3.0e38f; }
                if (Msk[c + 1]) { sf[nt][1] = -3.0e38f; sf[nt][3] = -3.0e38f; }
            }
        }

        // ---- Online softmax (rows g and g+8) ----
        float cm_lo = -1e30f, cm_hi = -1e30f;
        #pragma unroll
        for (int nt = 0; nt < 8; nt++) {
            cm_lo = fmaxf(cm_lo, fmaxf(sf[nt][0], sf[nt][1]));
            cm_hi = fmaxf(cm_hi, fmaxf(sf[nt][2], sf[nt][3]));
        }
        cm_lo = fmaxf(cm_lo, __shfl_xor_sync(0xffffffffu, cm_lo, 1));
        cm_lo = fmaxf(cm_lo, __shfl_xor_sync(0xffffffffu, cm_lo, 2));
        cm_hi = fmaxf(cm_hi, __shfl_xor_sync(0xffffffffu, cm_hi, 1));
        cm_hi = fmaxf(cm_hi, __shfl_xor_sync(0xffffffffu, cm_hi, 2));

        const float mn_lo = fmaxf(m_lo, cm_lo);
        const float mn_hi = fmaxf(m_hi, cm_hi);
        const float al_lo = __expf(m_lo - mn_lo);
        const float al_hi = __expf(m_hi - mn_hi);
        l_lo *= al_lo; l_hi *= al_hi;
        #pragma unroll
        for (int nt = 0; nt < 4; nt++) {
            of[nt][0] *= al_lo; of[nt][1] *= al_lo;
            of[nt][2] *= al_hi; of[nt][3] *= al_hi;
        }

        float rs_lo = 0.0f, rs_hi = 0.0f;
        #pragma unroll
        for (int nt = 0; nt < 8; nt++) {
            const float p0 = __expf(sf[nt][0] - mn_lo);
            const float p1 = __expf(sf[nt][1] - mn_lo);
            const float p2 = __expf(sf[nt][2] - mn_hi);
            const float p3 = __expf(sf[nt][3] - mn_hi);
            rs_lo += p0 + p1;
            rs_hi += p2 + p3;
            sf[nt][0] = f2tf32f(p0); sf[nt][1] = f2tf32f(p1);
            sf[nt][2] = f2tf32f(p2); sf[nt][3] = f2tf32f(p3);
        }
        rs_lo += __shfl_xor_sync(0xffffffffu, rs_lo, 1);
        rs_lo += __shfl_xor_sync(0xffffffffu, rs_lo, 2);
        rs_hi += __shfl_xor_sync(0xffffffffu, rs_hi, 1);
        rs_hi += __shfl_xor_sync(0xffffffffu, rs_hi, 2);
        l_lo += rs_lo; l_hi += rs_hi;
        m_lo = mn_lo; m_hi = mn_hi;

        // ---- PV: O (16x32) += P (16x64) @ V (64x32) ----
        // P C-layout -> A-layout via shuffles; keys in steps of 8.
        #pragma unroll
        for (int kt = 0; kt < 8; kt++) {
            const int src = g * 4 + (t >> 1);          // holder of col kt*8+t
            const float x0  = __shfl_sync(0xffffffffu, sf[kt][0], src);
            const float x1  = __shfl_sync(0xffffffffu, sf[kt][1], src);
            const float y0  = __shfl_sync(0xffffffffu, sf[kt][2], src);
            const float y1  = __shfl_sync(0xffffffffu, sf[kt][3], src);
            const float x0b = __shfl_sync(0xffffffffu, sf[kt][0], src + 2);
            const float x1b = __shfl_sync(0xffffffffu, sf[kt][1], src + 2);
            const float y0b = __shfl_sync(0xffffffffu, sf[kt][2], src + 2);
            const float y1b = __shfl_sync(0xffffffffu, sf[kt][3], src + 2);
            const bool odd = (t & 1);
            const uint32_t a0 = __float_as_uint(odd ? x1  : x0 );
            const uint32_t a1 = __float_as_uint(odd ? y1  : y0 );
            const uint32_t a2 = __float_as_uint(odd ? x1b : x0b);
            const uint32_t a3 = __float_as_uint(odd ? y1b : y0b);
            #pragma unroll
            for (int nt = 0; nt < 4; nt++) {
                const uint32_t b0 = __float_as_uint(Vs[kt * 8 + t    ][nt * 8 + g]);
                const uint32_t b1 = __float_as_uint(Vs[kt * 8 + t + 4][nt * 8 + g]);
                mma_tf32(of[nt], a0, a1, a2, a3, b0, b1);
            }
        }
    }

    // ---- Write output (merged heads) ----
    const float inv_lo = 1.0f / l_lo;
    const float inv_hi = 1.0f / l_hi;
    const size_t r_lo = (size_t)b * Lq + q0 + 16 * w + g;
    const size_t r_hi = r_lo + 8;
    #pragma unroll
    for (int nt = 0; nt < 4; nt++) {
        const int col = h * 32 + nt * 8 + 2 * t;
        float2 lo = make_float2(of[nt][0] * inv_lo, of[nt][1] * inv_lo);
        float2 hi = make_float2(of[nt][2] * inv_hi, of[nt][3] * inv_hi);
        *(float2*)&Op[r_lo * 256 + col] = lo;
        *(float2*)&Op[r_hi * 256 + col] = hi;
    }
}

// ---------------------------------------------------------------------------
extern "C" void kernel_launch(void* const* d_in, const int* in_sizes, int n_in,
                              void* d_out, int out_size)
{
    const float* amr      = (const float*)d_in[0];
    const int*   pad_mask = (const int*)  d_in[1];
    const float* vis      = (const float*)d_in[2];
    const float* W_amr_qk = (const float*)d_in[3];
    const float* W_amr_v  = (const float*)d_in[4];
    const float* W_vis_qk = (const float*)d_in[5];
    const float* W_vis_v  = (const float*)d_in[6];
    const float* W_amr_out= (const float*)d_in[7];
    const float* b_amr_out= (const float*)d_in[8];
    const float* W_vis_out= (const float*)d_in[9];
    const float* b_vis_out= (const float*)d_in[10];

    float* out_amr = (float*)d_out;                       // [4,512,256]
    float* out_vis = out_amr + (size_t)BB * NN * DD;      // [4,4096,256]

    float *amr_qk, *amr_v, *vis_qk, *vis_v, *amr_att, *vis_att;
    cudaGetSymbolAddress((void**)&amr_qk,  g_amr_qk);
    cudaGetSymbolAddress((void**)&amr_v,   g_amr_v);
    cudaGetSymbolAddress((void**)&vis_qk,  g_vis_qk);
    cudaGetSymbolAddress((void**)&vis_v,   g_vis_v);
    cudaGetSymbolAddress((void**)&amr_att, g_amr_att);
    cudaGetSymbolAddress((void**)&vis_att, g_vis_att);

    const dim3 gA(4, (BB * NN) / 64);   // 2048 rows
    const dim3 gV(4, (BB * MM) / 64);   // 16384 rows

    // Projections (tf32 tensor cores)
    gemm_mma<false><<<gA, 128>>>(amr, W_amr_qk, nullptr, nullptr, amr_qk);
    gemm_mma<false><<<gA, 128>>>(amr, W_amr_v,  nullptr, nullptr, amr_v);
    gemm_mma<false><<<gV, 128>>>(vis, W_vis_qk, nullptr, nullptr, vis_qk);
    gemm_mma<false><<<gV, 128>>>(vis, W_vis_v,  nullptr, nullptr, vis_v);

    // Direction 1: amr -> visual (no mask), softmax over M
    attn_mma<<<dim3(NN / 64, HH, BB), 128>>>(amr_qk, vis_qk, vis_v, amr_att,
                                             nullptr, NN, MM);
    // Direction 2: visual -> amr (key mask = amr_pad_mask), softmax over N
    attn_mma<<<dim3(MM / 64, HH, BB), 128>>>(vis_qk, amr_qk, amr_v, vis_att,
                                             pad_mask, MM, NN);

    // Output projections with fused bias + elementwise gate
    gemm_mma<true><<<gA, 128>>>(amr_att, W_amr_out, b_amr_out, amr, out_amr);
    gemm_mma<true><<<gV, 128>>>(vis_att, W_vis_out, b_vis_out, vis, out_vis);
}

// round 6
// speedup vs baseline: 3.7460x; 1.5665x over previous
#include <cuda_runtime.h>
#include <math.h>
#include <stdint.h>

// Problem constants
#define BB 4
#define NN 512
#define MM 4096
#define DD 256
#define HH 8
#define SCALE 0.17677669529663687f           // 1/sqrt(32)
#define C2EXP 0.25505551190558915f           // SCALE * log2(e)

// ---------------------------------------------------------------------------
// Scratch (static device globals)
// ---------------------------------------------------------------------------
__device__ float g_amr_t [BB*NN*DD];         // tf32-rounded inputs
__device__ float g_vis_t [BB*MM*DD];
__device__ float g_Wt    [6*DD*DD];          // transposed+rounded weights [n][k]
__device__ float g_amr_qk[BB*NN*DD];
__device__ float g_amr_v [BB*NN*DD];
__device__ float g_vis_qk[BB*MM*DD];
__device__ float g_vis_v [BB*MM*DD];
__device__ float g_amr_att[BB*NN*DD];
__device__ float g_vis_att[BB*MM*DD];
__device__ float g_po    [2*BB*NN*DD];       // dir1 split partial O (unnormalized)
__device__ float g_pl    [2*BB*HH*NN];       // dir1 split partial l

// ---------------------------------------------------------------------------
// Helpers
// ---------------------------------------------------------------------------
__device__ __forceinline__ float f2tf32f(float f) {
    uint32_t r;
    asm("cvt.rna.tf32.f32 %0, %1;" : "=r"(r) : "f"(f));
    return __uint_as_float(r);
}

__device__ __forceinline__ float ex2f(float x) {
    float r;
    asm("ex2.approx.f32 %0, %1;" : "=f"(r) : "f"(x));
    return r;
}

__device__ __forceinline__ void mma_tf32(float c[4],
                                         uint32_t a0, uint32_t a1,
                                         uint32_t a2, uint32_t a3,
                                         uint32_t b0, uint32_t b1) {
    asm volatile(
        "mma.sync.aligned.m16n8k8.row.col.f32.tf32.tf32.f32 "
        "{%0,%1,%2,%3}, {%4,%5,%6,%7}, {%8,%9}, {%0,%1,%2,%3};"
        : "+f"(c[0]), "+f"(c[1]), "+f"(c[2]), "+f"(c[3])
        : "r"(a0), "r"(a1), "r"(a2), "r"(a3), "r"(b0), "r"(b1));
}

__device__ __forceinline__ uint32_t smem_u32(const void* p) {
    return (uint32_t)__cvta_generic_to_shared(p);
}

#define CP16(dst_u32, src) \
    asm volatile("cp.async.ca.shared.global [%0], [%1], 16;" \
                 :: "r"(dst_u32), "l"(src))
#define CP_COMMIT() asm volatile("cp.async.commit_group;")
#define CP_WAIT(n)  asm volatile("cp.async.wait_group %0;" :: "n"(n))

// ---------------------------------------------------------------------------
// Prep: tf32-round an array (n divisible by 1024)
// ---------------------------------------------------------------------------
__global__ void round_tf32(const float* __restrict__ in,
                           float* __restrict__ out, int n)
{
    const int i4 = (blockIdx.x * 256 + threadIdx.x) * 4;
    if (i4 < n) {
        const float4 v = *(const float4*)&in[i4];
        float4 o;
        o.x = f2tf32f(v.x); o.y = f2tf32f(v.y);
        o.z = f2tf32f(v.z); o.w = f2tf32f(v.w);
        *(float4*)&out[i4] = o;
    }
}

// Prep: transpose+round 6 weight matrices: Wt[m][n][k] = tf32(W[m][k][n])
__global__ void transpose_w(const float* W0, const float* W1, const float* W2,
                            const float* W3, const float* W4, const float* W5,
                            float* __restrict__ Wt)
{
    __shared__ float tile[32][33];
    const float* Ws[6] = {W0, W1, W2, W3, W4, W5};
    const float* in = Ws[blockIdx.z];
    float* out = Wt + (size_t)blockIdx.z * DD * DD;
    const int x0 = blockIdx.x * 32;      // n
    const int y0 = blockIdx.y * 32;      // k
    const int tx = threadIdx.x, ty = threadIdx.y;
    #pragma unroll
    for (int j = 0; j < 32; j += 8)
        tile[ty + j][tx] = f2tf32f(in[(size_t)(y0 + ty + j) * DD + x0 + tx]);
    __syncthreads();
    #pragma unroll
    for (int j = 0; j < 32; j += 8)
        out[(size_t)(x0 + ty + j) * DD + y0 + tx] = tile[tx][ty + j];
}

// ---------------------------------------------------------------------------
// tf32 GEMM, cp.async 2-stage: C[S,256] = A[S,256] @ W[256,256]
// A pre-rounded [row][k]; Wt pre-rounded transposed [n][k].
// 128 threads, 4 warps, 64x64 tile. PROJ: out rounded. EPI: (acc+bias)*Xm raw.
// ---------------------------------------------------------------------------
template <bool EPI>
__global__ void __launch_bounds__(128) gemm2(const float* __restrict__ A,
                                             const float* __restrict__ Wt,
                                             const float* __restrict__ bias,
                                             const float* __restrict__ Xm,
                                             float* __restrict__ C)
{
    __shared__ float Ab[2][64][36];
    __shared__ float Wb[2][64][36];

    const int row0 = blockIdx.y * 64;
    const int col0 = blockIdx.x * 64;
    const int tid  = threadIdx.x;
    const int w    = tid >> 5;
    const int lane = tid & 31;
    const int g    = lane >> 2;
    const int t    = lane & 3;
    const int sr   = tid >> 3;            // staging row 0..15 (x4 strided)
    const int sc   = (tid & 7) * 4;       // staging col

    float acc[8][4];
    #pragma unroll
    for (int nt = 0; nt < 8; nt++)
        #pragma unroll
        for (int i = 0; i < 4; i++) acc[nt][i] = 0.0f;

    // Stage chunk kc into buffer s
    auto stage = [&](int s, int kc) {
        #pragma unroll
        for (int rr = 0; rr < 64; rr += 16) {
            const int r = sr + rr;
            CP16(smem_u32(&Ab[s][r][sc]), &A [(size_t)(row0 + r) * 256 + kc + sc]);
            CP16(smem_u32(&Wb[s][r][sc]), &Wt[(size_t)(col0 + r) * 256 + kc + sc]);
        }
    };

    stage(0, 0); CP_COMMIT();

    for (int c = 0; c < 8; c++) {
        if (c < 7) { stage((c + 1) & 1, (c + 1) * 32); CP_COMMIT(); CP_WAIT(1); }
        else       { CP_WAIT(0); }
        __syncthreads();
        const int s = c & 1;
        #pragma unroll
        for (int kk = 0; kk < 4; kk++) {
            const int k8 = kk * 8;
            const uint32_t a0 = __float_as_uint(Ab[s][16 * w + g    ][k8 + t    ]);
            const uint32_t a1 = __float_as_uint(Ab[s][16 * w + g + 8][k8 + t    ]);
            const uint32_t a2 = __float_as_uint(Ab[s][16 * w + g    ][k8 + t + 4]);
            const uint32_t a3 = __float_as_uint(Ab[s][16 * w + g + 8][k8 + t + 4]);
            #pragma unroll
            for (int nt = 0; nt < 8; nt++) {
                const uint32_t b0 = __float_as_uint(Wb[s][nt * 8 + g][k8 + t    ]);
                const uint32_t b1 = __float_as_uint(Wb[s][nt * 8 + g][k8 + t + 4]);
                mma_tf32(acc[nt], a0, a1, a2, a3, b0, b1);
            }
        }
        __syncthreads();
    }

    const size_t r_lo = (size_t)(row0 + 16 * w + g);
    const size_t r_hi = r_lo + 8;
    #pragma unroll
    for (int nt = 0; nt < 8; nt++) {
        const int col = col0 + nt * 8 + 2 * t;
        float2 lo = make_float2(acc[nt][0], acc[nt][1]);
        float2 hi = make_float2(acc[nt][2], acc[nt][3]);
        if (EPI) {
            const float2 bv  = *(const float2*)&bias[col];
            const float2 xlo = *(const float2*)&Xm[r_lo * 256 + col];
            const float2 xhi = *(const float2*)&Xm[r_hi * 256 + col];
            lo.x = (lo.x + bv.x) * xlo.x; lo.y = (lo.y + bv.y) * xlo.y;
            hi.x = (hi.x + bv.x) * xhi.x; hi.y = (hi.y + bv.y) * xhi.y;
        } else {
            lo.x = f2tf32f(lo.x); lo.y = f2tf32f(lo.y);   // feeds attention mma
            hi.x = f2tf32f(hi.x); hi.y = f2tf32f(hi.y);
        }
        *(float2*)&C[r_lo * 256 + col] = lo;
        *(float2*)&C[r_hi * 256 + col] = hi;
    }
}

// ---------------------------------------------------------------------------
// Flash cross-attention, tf32 mma, cp.async 2-stage, no online max.
// All mma inputs pre-tf32-rounded. Scale folded into exp2 constant.
// norm=false: writes unnormalized O + per-row l (split-KV partials).
// Grid: (Lq/64 [* splits via separate launches], H, B), 128 threads.
// ---------------------------------------------------------------------------
__global__ void __launch_bounds__(128) attn2(const float* __restrict__ Qp,
                                             const float* __restrict__ Kp,
                                             const float* __restrict__ Vp,
                                             float* __restrict__ Op,
                                             float* __restrict__ Lp,
                                             const int* __restrict__ mask,
                                             int Lq, int LkT, int kv0, int kvlen,
                                             int norm)
{
    __shared__ float Qs[64][36];
    __shared__ float Kb[2][64][36];
    __shared__ float Vb[2][64][40];
    __shared__ int   Mskb[2][64];

    const int b  = blockIdx.z;
    const int h  = blockIdx.y;
    const int q0 = blockIdx.x * 64;
    const int tid  = threadIdx.x;
    const int w    = tid >> 5;
    const int lane = tid & 31;
    const int g    = lane >> 2;
    const int t    = lane & 3;
    const int sr   = tid >> 3;
    const int sc   = (tid & 7) * 4;

    auto stageKV = [&](int s, int kc) {
        #pragma unroll
        for (int rr = 0; rr < 64; rr += 16) {
            const int r = sr + rr;
            const size_t base = ((size_t)b * LkT + kv0 + kc + r) * 256 + h * 32 + sc;
            CP16(smem_u32(&Kb[s][r][sc]), &Kp[base]);
            CP16(smem_u32(&Vb[s][r][sc]), &Vp[base]);
        }
        if (mask && tid < 16)
            CP16(smem_u32(&Mskb[s][tid * 4]), &mask[b * LkT + kv0 + kc + tid * 4]);
    };

    // Stage Q (once) + first K/V chunk in group 0
    #pragma unroll
    for (int rr = 0; rr < 64; rr += 16) {
        const int r = sr + rr;
        CP16(smem_u32(&Qs[r][sc]),
             &Qp[((size_t)b * Lq + q0 + r) * 256 + h * 32 + sc]);
    }
    stageKV(0, 0);
    CP_COMMIT();

    uint32_t qa[4][4];
    float of[4][4];
    #pragma unroll
    for (int nt = 0; nt < 4; nt++)
        #pragma unroll
        for (int i = 0; i < 4; i++) of[nt][i] = 0.0f;
    float l_lo = 0.0f, l_hi = 0.0f;

    const int nchunks = kvlen / 64;
    for (int c = 0; c < nchunks; c++) {
        if (c + 1 < nchunks) { stageKV((c + 1) & 1, (c + 1) * 64); CP_COMMIT(); CP_WAIT(1); }
        else                 { CP_WAIT(0); }
        __syncthreads();
        const int s = c & 1;

        if (c == 0) {
            #pragma unroll
            for (int kk = 0; kk < 4; kk++) {
                const int k8 = kk * 8;
                qa[kk][0] = __float_as_uint(Qs[16 * w + g    ][k8 + t    ]);
                qa[kk][1] = __float_as_uint(Qs[16 * w + g + 8][k8 + t    ]);
                qa[kk][2] = __float_as_uint(Qs[16 * w + g    ][k8 + t + 4]);
                qa[kk][3] = __float_as_uint(Qs[16 * w + g + 8][k8 + t + 4]);
            }
        }

        // ---- Scores: S (16x64 per warp) = Q K^T ----
        float sf[8][4];
        #pragma unroll
        for (int nt = 0; nt < 8; nt++) {
            sf[nt][0] = 0.0f; sf[nt][1] = 0.0f; sf[nt][2] = 0.0f; sf[nt][3] = 0.0f;
            #pragma unroll
            for (int kk = 0; kk < 4; kk++) {
                const int k8 = kk * 8;
                const uint32_t b0 = __float_as_uint(Kb[s][nt * 8 + g][k8 + t    ]);
                const uint32_t b1 = __float_as_uint(Kb[s][nt * 8 + g][k8 + t + 4]);
                mma_tf32(sf[nt], qa[kk][0], qa[kk][1], qa[kk][2], qa[kk][3], b0, b1);
            }
        }

        // ---- exp (scale folded), mask, l accumulate, p -> tf32 ----
        #pragma unroll
        for (int nt = 0; nt < 8; nt++) {
            float p0 = ex2f(sf[nt][0] * C2EXP);
            float p1 = ex2f(sf[nt][1] * C2EXP);
            float p2 = ex2f(sf[nt][2] * C2EXP);
            float p3 = ex2f(sf[nt][3] * C2EXP);
            if (mask) {
                const int cbase = nt * 8 + 2 * t;
                if (Mskb[s][cbase    ]) { p0 = 0.0f; p2 = 0.0f; }
                if (Mskb[s][cbase + 1]) { p1 = 0.0f; p3 = 0.0f; }
            }
            l_lo += p0 + p1;
            l_hi += p2 + p3;
            sf[nt][0] = f2tf32f(p0); sf[nt][1] = f2tf32f(p1);
            sf[nt][2] = f2tf32f(p2); sf[nt][3] = f2tf32f(p3);
        }

        // ---- PV: O (16x32) += P (16x64) @ V (64x32) ----
        #pragma unroll
        for (int kt = 0; kt < 8; kt++) {
            const int src = g * 4 + (t >> 1);
            const float x0  = __shfl_sync(0xffffffffu, sf[kt][0], src);
            const float x1  = __shfl_sync(0xffffffffu, sf[kt][1], src);
            const float y0  = __shfl_sync(0xffffffffu, sf[kt][2], src);
            const float y1  = __shfl_sync(0xffffffffu, sf[kt][3], src);
            const float x0b = __shfl_sync(0xffffffffu, sf[kt][0], src + 2);
            const float x1b = __shfl_sync(0xffffffffu, sf[kt][1], src + 2);
            const float y0b = __shfl_sync(0xffffffffu, sf[kt][2], src + 2);
            const float y1b = __shfl_sync(0xffffffffu, sf[kt][3], src + 2);
            const bool odd = (t & 1);
            const uint32_t a0 = __float_as_uint(odd ? x1  : x0 );
            const uint32_t a1 = __float_as_uint(odd ? y1  : y0 );
            const uint32_t a2 = __float_as_uint(odd ? x1b : x0b);
            const uint32_t a3 = __float_as_uint(odd ? y1b : y0b);
            #pragma unroll
            for (int nt = 0; nt < 4; nt++) {
                const uint32_t b0 = __float_as_uint(Vb[s][kt * 8 + t    ][nt * 8 + g]);
                const uint32_t b1 = __float_as_uint(Vb[s][kt * 8 + t + 4][nt * 8 + g]);
                mma_tf32(of[nt], a0, a1, a2, a3, b0, b1);
            }
        }
        __syncthreads();
    }

    // ---- l reduce across t lanes ----
    l_lo += __shfl_xor_sync(0xffffffffu, l_lo, 1);
    l_lo += __shfl_xor_sync(0xffffffffu, l_lo, 2);
    l_hi += __shfl_xor_sync(0xffffffffu, l_hi, 1);
    l_hi += __shfl_xor_sync(0xffffffffu, l_hi, 2);

    const size_t r_lo = (size_t)b * Lq + q0 + 16 * w + g;
    const size_t r_hi = r_lo + 8;
    if (norm) {
        const float inv_lo = 1.0f / l_lo;
        const float inv_hi = 1.0f / l_hi;
        #pragma unroll
        for (int nt = 0; nt < 4; nt++) {
            const int col = h * 32 + nt * 8 + 2 * t;
            float2 lo, hi;
            lo.x = f2tf32f(of[nt][0] * inv_lo); lo.y = f2tf32f(of[nt][1] * inv_lo);
            hi.x = f2tf32f(of[nt][2] * inv_hi); hi.y = f2tf32f(of[nt][3] * inv_hi);
            *(float2*)&Op[r_lo * 256 + col] = lo;
            *(float2*)&Op[r_hi * 256 + col] = hi;
        }
    } else {
        #pragma unroll
        for (int nt = 0; nt < 4; nt++) {
            const int col = h * 32 + nt * 8 + 2 * t;
            *(float2*)&Op[r_lo * 256 + col] = make_float2(of[nt][0], of[nt][1]);
            *(float2*)&Op[r_hi * 256 + col] = make_float2(of[nt][2], of[nt][3]);
        }
        if (t == 0) {
            Lp[((size_t)b * HH + h) * Lq + q0 + 16 * w + g    ] = l_lo;
            Lp[((size_t)b * HH + h) * Lq + q0 + 16 * w + g + 8] = l_hi;
        }
    }
}

// ---------------------------------------------------------------------------
// Combine dir1 split partials: out = tf32((O0+O1)/(l0+l1))
// ---------------------------------------------------------------------------
__global__ void combine2(const float* __restrict__ po,
                         const float* __restrict__ pl,
                         float* __restrict__ out)
{
    const int i4 = (blockIdx.x * 256 + threadIdx.x) * 4;
    if (i4 >= BB * NN * DD) return;
    const int b = i4 / (NN * DD);
    const int rem = i4 - b * NN * DD;
    const int q = rem / DD;
    const int c = rem - q * DD;
    const int h = c >> 5;
    const float l = pl[((size_t)b * HH + h) * NN + q] +
                    pl[(size_t)BB * HH * NN + ((size_t)b * HH + h) * NN + q];
    const float inv = 1.0f / l;
    const float4 o0 = *(const float4*)&po[i4];
    const float4 o1 = *(const float4*)&po[BB * NN * DD + i4];
    float4 o;
    o.x = f2tf32f((o0.x + o1.x) * inv);
    o.y = f2tf32f((o0.y + o1.y) * inv);
    o.z = f2tf32f((o0.z + o1.z) * inv);
    o.w = f2tf32f((o0.w + o1.w) * inv);
    *(float4*)&out[i4] = o;
}

// ---------------------------------------------------------------------------
extern "C" void kernel_launch(void* const* d_in, const int* in_sizes, int n_in,
                              void* d_out, int out_size)
{
    const float* amr      = (const float*)d_in[0];
    const int*   pad_mask = (const int*)  d_in[1];
    const float* vis      = (const float*)d_in[2];
    const float* W_amr_qk = (const float*)d_in[3];
    const float* W_amr_v  = (const float*)d_in[4];
    const float* W_vis_qk = (const float*)d_in[5];
    const float* W_vis_v  = (const float*)d_in[6];
    const float* W_amr_out= (const float*)d_in[7];
    const float* b_amr_out= (const float*)d_in[8];
    const float* W_vis_out= (const float*)d_in[9];
    const float* b_vis_out= (const float*)d_in[10];

    float* out_amr = (float*)d_out;
    float* out_vis = out_amr + (size_t)BB * NN * DD;

    float *amr_t, *vis_t, *Wt, *amr_qk, *amr_v, *vis_qk, *vis_v;
    float *amr_att, *vis_att, *po, *pl;
    cudaGetSymbolAddress((void**)&amr_t,   g_amr_t);
    cudaGetSymbolAddress((void**)&vis_t,   g_vis_t);
    cudaGetSymbolAddress((void**)&Wt,      g_Wt);
    cudaGetSymbolAddress((void**)&amr_qk,  g_amr_qk);
    cudaGetSymbolAddress((void**)&amr_v,   g_amr_v);
    cudaGetSymbolAddress((void**)&vis_qk,  g_vis_qk);
    cudaGetSymbolAddress((void**)&vis_v,   g_vis_v);
    cudaGetSymbolAddress((void**)&amr_att, g_amr_att);
    cudaGetSymbolAddress((void**)&vis_att, g_vis_att);
    cudaGetSymbolAddress((void**)&po,      g_po);
    cudaGetSymbolAddress((void**)&pl,      g_pl);

    // --- Prep: round inputs, transpose+round weights ---
    round_tf32<<<(BB*NN*DD)/1024, 256>>>(amr, amr_t, BB*NN*DD);
    round_tf32<<<(BB*MM*DD)/1024, 256>>>(vis, vis_t, BB*MM*DD);
    transpose_w<<<dim3(8, 8, 6), dim3(32, 8)>>>(W_amr_qk, W_amr_v, W_vis_qk,
                                                W_vis_v, W_amr_out, W_vis_out, Wt);

    const dim3 gA(4, (BB * NN) / 64);
    const dim3 gV(4, (BB * MM) / 64);

    // --- Projections ---
    gemm2<false><<<gA, 128>>>(amr_t, Wt + 0*DD*DD, nullptr, nullptr, amr_qk);
    gemm2<false><<<gA, 128>>>(amr_t, Wt + 1*DD*DD, nullptr, nullptr, amr_v);
    gemm2<false><<<gV, 128>>>(vis_t, Wt + 2*DD*DD, nullptr, nullptr, vis_qk);
    gemm2<false><<<gV, 128>>>(vis_t, Wt + 3*DD*DD, nullptr, nullptr, vis_v);

    // --- Dir 1: amr -> visual, split-KV x2 (unnormalized partials) ---
    attn2<<<dim3(NN/64, HH, BB), 128>>>(amr_qk, vis_qk, vis_v,
                                        po,                    pl,
                                        nullptr, NN, MM, 0,    MM/2, 0);
    attn2<<<dim3(NN/64, HH, BB), 128>>>(amr_qk, vis_qk, vis_v,
                                        po + (size_t)BB*NN*DD, pl + BB*HH*NN,
                                        nullptr, NN, MM, MM/2, MM/2, 0);
    combine2<<<(BB*NN*DD)/1024, 256>>>(po, pl, amr_att);

    // --- Dir 2: visual -> amr, masked keys, single pass normalized ---
    attn2<<<dim3(MM/64, HH, BB), 128>>>(vis_qk, amr_qk, amr_v,
                                        vis_att, nullptr,
                                        pad_mask, MM, NN, 0, NN, 1);

    // --- Output projections with fused bias + gate (raw-precision gate) ---
    gemm2<true><<<gA, 128>>>(amr_att, Wt + 4*DD*DD, b_amr_out, amr, out_amr);
    gemm2<true><<<gV, 128>>>(vis_att, Wt + 5*DD*DD, b_vis_out, vis, out_vis);
}

// round 7
// speedup vs baseline: 3.7464x; 1.0001x over previous
#include <cuda_runtime.h>
#include <math.h>
#include <stdint.h>

// Problem constants
#define BB 4
#define NN 512
#define MM 4096
#define DD 256
#define HH 8
#define SCALE 0.17677669529663687f           // 1/sqrt(32)
#define C2EXP 0.25505551190558915f           // SCALE * log2(e)

// ---------------------------------------------------------------------------
// Scratch (static device globals)
// ---------------------------------------------------------------------------
__device__ float g_amr_t [BB*NN*DD];         // tf32-rounded inputs
__device__ float g_vis_t [BB*MM*DD];
__device__ float g_Wt    [6*DD*DD];          // transposed+rounded weights [n][k]
__device__ float g_amr_qk[BB*NN*DD];
__device__ float g_amr_v [BB*NN*DD];
__device__ float g_vis_qk[BB*MM*DD];
__device__ float g_vis_v [BB*MM*DD];
__device__ float g_amr_att[BB*NN*DD];
__device__ float g_vis_att[BB*MM*DD];
__device__ float g_po    [2*BB*NN*DD];       // dir1 split partial O (unnormalized)
__device__ float g_pl    [2*BB*HH*NN];       // dir1 split partial l

// ---------------------------------------------------------------------------
// Helpers
// ---------------------------------------------------------------------------
__device__ __forceinline__ float f2tf32f(float f) {
    uint32_t r;
    asm("cvt.rna.tf32.f32 %0, %1;" : "=r"(r) : "f"(f));
    return __uint_as_float(r);
}

__device__ __forceinline__ float ex2f(float x) {
    float r;
    asm("ex2.approx.f32 %0, %1;" : "=f"(r) : "f"(x));
    return r;
}

__device__ __forceinline__ void mma_tf32(float c[4],
                                         uint32_t a0, uint32_t a1,
                                         uint32_t a2, uint32_t a3,
                                         uint32_t b0, uint32_t b1) {
    asm volatile(
        "mma.sync.aligned.m16n8k8.row.col.f32.tf32.tf32.f32 "
        "{%0,%1,%2,%3}, {%4,%5,%6,%7}, {%8,%9}, {%0,%1,%2,%3};"
        : "+f"(c[0]), "+f"(c[1]), "+f"(c[2]), "+f"(c[3])
        : "r"(a0), "r"(a1), "r"(a2), "r"(a3), "r"(b0), "r"(b1));
}

__device__ __forceinline__ uint32_t smem_u32(const void* p) {
    return (uint32_t)__cvta_generic_to_shared(p);
}

#define CP16(dst_u32, src) \
    asm volatile("cp.async.ca.shared.global [%0], [%1], 16;" \
                 :: "r"(dst_u32), "l"(src))
#define CP_COMMIT() asm volatile("cp.async.commit_group;")
#define CP_WAIT(n)  asm volatile("cp.async.wait_group %0;" :: "n"(n))

// ---------------------------------------------------------------------------
// Prep: tf32-round an array (n divisible by 1024)
// ---------------------------------------------------------------------------
__global__ void round_tf32(const float* __restrict__ in,
                           float* __restrict__ out, int n)
{
    const int i4 = (blockIdx.x * 256 + threadIdx.x) * 4;
    if (i4 < n) {
        const float4 v = *(const float4*)&in[i4];
        float4 o;
        o.x = f2tf32f(v.x); o.y = f2tf32f(v.y);
        o.z = f2tf32f(v.z); o.w = f2tf32f(v.w);
        *(float4*)&out[i4] = o;
    }
}

// Prep: transpose+round 6 weight matrices: Wt[m][n][k] = tf32(W[m][k][n])
__global__ void transpose_w(const float* W0, const float* W1, const float* W2,
                            const float* W3, const float* W4, const float* W5,
                            float* __restrict__ Wt)
{
    __shared__ float tile[32][33];
    const float* Ws[6] = {W0, W1, W2, W3, W4, W5};
    const float* in = Ws[blockIdx.z];
    float* out = Wt + (size_t)blockIdx.z * DD * DD;
    const int x0 = blockIdx.x * 32;      // n
    const int y0 = blockIdx.y * 32;      // k
    const int tx = threadIdx.x, ty = threadIdx.y;
    #pragma unroll
    for (int j = 0; j < 32; j += 8)
        tile[ty + j][tx] = f2tf32f(in[(size_t)(y0 + ty + j) * DD + x0 + tx]);
    __syncthreads();
    #pragma unroll
    for (int j = 0; j < 32; j += 8)
        out[(size_t)(x0 + ty + j) * DD + y0 + tx] = tile[tx][ty + j];
}

// ---------------------------------------------------------------------------
// tf32 GEMM, cp.async 2-stage: C[S,256] = A[S,256] @ W[256,256]
// A pre-rounded [row][k]; Wt pre-rounded transposed [n][k].
// 128 threads, 4 warps, 64x64 tile. PROJ: out rounded. EPI: (acc+bias)*Xm raw.
// ---------------------------------------------------------------------------
template <bool EPI>
__global__ void __launch_bounds__(128) gemm2(const float* __restrict__ A,
                                             const float* __restrict__ Wt,
                                             const float* __restrict__ bias,
                                             const float* __restrict__ Xm,
                                             float* __restrict__ C)
{
    __shared__ float Ab[2][64][36];
    __shared__ float Wb[2][64][36];

    const int row0 = blockIdx.y * 64;
    const int col0 = blockIdx.x * 64;
    const int tid  = threadIdx.x;
    const int w    = tid >> 5;
    const int lane = tid & 31;
    const int g    = lane >> 2;
    const int t    = lane & 3;
    const int sr   = tid >> 3;            // staging row 0..15 (x4 strided)
    const int sc   = (tid & 7) * 4;       // staging col

    float acc[8][4];
    #pragma unroll
    for (int nt = 0; nt < 8; nt++)
        #pragma unroll
        for (int i = 0; i < 4; i++) acc[nt][i] = 0.0f;

    // Stage chunk kc into buffer s
    auto stage = [&](int s, int kc) {
        #pragma unroll
        for (int rr = 0; rr < 64; rr += 16) {
            const int r = sr + rr;
            CP16(smem_u32(&Ab[s][r][sc]), &A [(size_t)(row0 + r) * 256 + kc + sc]);
            CP16(smem_u32(&Wb[s][r][sc]), &Wt[(size_t)(col0 + r) * 256 + kc + sc]);
        }
    };

    stage(0, 0); CP_COMMIT();

    for (int c = 0; c < 8; c++) {
        if (c < 7) { stage((c + 1) & 1, (c + 1) * 32); CP_COMMIT(); CP_WAIT(1); }
        else       { CP_WAIT(0); }
        __syncthreads();
        const int s = c & 1;
        #pragma unroll
        for (int kk = 0; kk < 4; kk++) {
            const int k8 = kk * 8;
            const uint32_t a0 = __float_as_uint(Ab[s][16 * w + g    ][k8 + t    ]);
            const uint32_t a1 = __float_as_uint(Ab[s][16 * w + g + 8][k8 + t    ]);
            const uint32_t a2 = __float_as_uint(Ab[s][16 * w + g    ][k8 + t + 4]);
            const uint32_t a3 = __float_as_uint(Ab[s][16 * w + g + 8][k8 + t + 4]);
            #pragma unroll
            for (int nt = 0; nt < 8; nt++) {
                const uint32_t b0 = __float_as_uint(Wb[s][nt * 8 + g][k8 + t    ]);
                const uint32_t b1 = __float_as_uint(Wb[s][nt * 8 + g][k8 + t + 4]);
                mma_tf32(acc[nt], a0, a1, a2, a3, b0, b1);
            }
        }
        __syncthreads();
    }

    const size_t r_lo = (size_t)(row0 + 16 * w + g);
    const size_t r_hi = r_lo + 8;
    #pragma unroll
    for (int nt = 0; nt < 8; nt++) {
        const int col = col0 + nt * 8 + 2 * t;
        float2 lo = make_float2(acc[nt][0], acc[nt][1]);
        float2 hi = make_float2(acc[nt][2], acc[nt][3]);
        if (EPI) {
            const float2 bv  = *(const float2*)&bias[col];
            const float2 xlo = *(const float2*)&Xm[r_lo * 256 + col];
            const float2 xhi = *(const float2*)&Xm[r_hi * 256 + col];
            lo.x = (lo.x + bv.x) * xlo.x; lo.y = (lo.y + bv.y) * xlo.y;
            hi.x = (hi.x + bv.x) * xhi.x; hi.y = (hi.y + bv.y) * xhi.y;
        } else {
            lo.x = f2tf32f(lo.x); lo.y = f2tf32f(lo.y);   // feeds attention mma
            hi.x = f2tf32f(hi.x); hi.y = f2tf32f(hi.y);
        }
        *(float2*)&C[r_lo * 256 + col] = lo;
        *(float2*)&C[r_hi * 256 + col] = hi;
    }
}

// ---------------------------------------------------------------------------
// Flash cross-attention, tf32 mma, cp.async 2-stage, no online max.
// All mma inputs pre-tf32-rounded. Scale folded into exp2 constant.
// norm=false: writes unnormalized O + per-row l (split-KV partials).
// Grid: (Lq/64 [* splits via separate launches], H, B), 128 threads.
// ---------------------------------------------------------------------------
__global__ void __launch_bounds__(128) attn2(const float* __restrict__ Qp,
                                             const float* __restrict__ Kp,
                                             const float* __restrict__ Vp,
                                             float* __restrict__ Op,
                                             float* __restrict__ Lp,
                                             const int* __restrict__ mask,
                                             int Lq, int LkT, int kv0, int kvlen,
                                             int norm)
{
    __shared__ float Qs[64][36];
    __shared__ float Kb[2][64][36];
    __shared__ float Vb[2][64][40];
    __shared__ int   Mskb[2][64];

    const int b  = blockIdx.z;
    const int h  = blockIdx.y;
    const int q0 = blockIdx.x * 64;
    const int tid  = threadIdx.x;
    const int w    = tid >> 5;
    const int lane = tid & 31;
    const int g    = lane >> 2;
    const int t    = lane & 3;
    const int sr   = tid >> 3;
    const int sc   = (tid & 7) * 4;

    auto stageKV = [&](int s, int kc) {
        #pragma unroll
        for (int rr = 0; rr < 64; rr += 16) {
            const int r = sr + rr;
            const size_t base = ((size_t)b * LkT + kv0 + kc + r) * 256 + h * 32 + sc;
            CP16(smem_u32(&Kb[s][r][sc]), &Kp[base]);
            CP16(smem_u32(&Vb[s][r][sc]), &Vp[base]);
        }
        if (mask && tid < 16)
            CP16(smem_u32(&Mskb[s][tid * 4]), &mask[b * LkT + kv0 + kc + tid * 4]);
    };

    // Stage Q (once) + first K/V chunk in group 0
    #pragma unroll
    for (int rr = 0; rr < 64; rr += 16) {
        const int r = sr + rr;
        CP16(smem_u32(&Qs[r][sc]),
             &Qp[((size_t)b * Lq + q0 + r) * 256 + h * 32 + sc]);
    }
    stageKV(0, 0);
    CP_COMMIT();

    uint32_t qa[4][4];
    float of[4][4];
    #pragma unroll
    for (int nt = 0; nt < 4; nt++)
        #pragma unroll
        for (int i = 0; i < 4; i++) of[nt][i] = 0.0f;
    float l_lo = 0.0f, l_hi = 0.0f;

    const int nchunks = kvlen / 64;
    for (int c = 0; c < nchunks; c++) {
        if (c + 1 < nchunks) { stageKV((c + 1) & 1, (c + 1) * 64); CP_COMMIT(); CP_WAIT(1); }
        else                 { CP_WAIT(0); }
        __syncthreads();
        const int s = c & 1;

        if (c == 0) {
            #pragma unroll
            for (int kk = 0; kk < 4; kk++) {
                const int k8 = kk * 8;
                qa[kk][0] = __float_as_uint(Qs[16 * w + g    ][k8 + t    ]);
                qa[kk][1] = __float_as_uint(Qs[16 * w + g + 8][k8 + t    ]);
                qa[kk][2] = __float_as_uint(Qs[16 * w + g    ][k8 + t + 4]);
                qa[kk][3] = __float_as_uint(Qs[16 * w + g + 8][k8 + t + 4]);
            }
        }

        // ---- Scores: S (16x64 per warp) = Q K^T ----
        float sf[8][4];
        #pragma unroll
        for (int nt = 0; nt < 8; nt++) {
            sf[nt][0] = 0.0f; sf[nt][1] = 0.0f; sf[nt][2] = 0.0f; sf[nt][3] = 0.0f;
            #pragma unroll
            for (int kk = 0; kk < 4; kk++) {
                const int k8 = kk * 8;
                const uint32_t b0 = __float_as_uint(Kb[s][nt * 8 + g][k8 + t    ]);
                const uint32_t b1 = __float_as_uint(Kb[s][nt * 8 + g][k8 + t + 4]);
                mma_tf32(sf[nt], qa[kk][0], qa[kk][1], qa[kk][2], qa[kk][3], b0, b1);
            }
        }

        // ---- exp (scale folded), mask, l accumulate, p -> tf32 ----
        #pragma unroll
        for (int nt = 0; nt < 8; nt++) {
            float p0 = ex2f(sf[nt][0] * C2EXP);
            float p1 = ex2f(sf[nt][1] * C2EXP);
            float p2 = ex2f(sf[nt][2] * C2EXP);
            float p3 = ex2f(sf[nt][3] * C2EXP);
            if (mask) {
                const int cbase = nt * 8 + 2 * t;
                if (Mskb[s][cbase    ]) { p0 = 0.0f; p2 = 0.0f; }
                if (Mskb[s][cbase + 1]) { p1 = 0.0f; p3 = 0.0f; }
            }
            l_lo += p0 + p1;
            l_hi += p2 + p3;
            sf[nt][0] = f2tf32f(p0); sf[nt][1] = f2tf32f(p1);
            sf[nt][2] = f2tf32f(p2); sf[nt][3] = f2tf32f(p3);
        }

        // ---- PV: O (16x32) += P (16x64) @ V (64x32) ----
        #pragma unroll
        for (int kt = 0; kt < 8; kt++) {
            const int src = g * 4 + (t >> 1);
            const float x0  = __shfl_sync(0xffffffffu, sf[kt][0], src);
            const float x1  = __shfl_sync(0xffffffffu, sf[kt][1], src);
            const float y0  = __shfl_sync(0xffffffffu, sf[kt][2], src);
            const float y1  = __shfl_sync(0xffffffffu, sf[kt][3], src);
            const float x0b = __shfl_sync(0xffffffffu, sf[kt][0], src + 2);
            const float x1b = __shfl_sync(0xffffffffu, sf[kt][1], src + 2);
            const float y0b = __shfl_sync(0xffffffffu, sf[kt][2], src + 2);
            const float y1b = __shfl_sync(0xffffffffu, sf[kt][3], src + 2);
            const bool odd = (t & 1);
            const uint32_t a0 = __float_as_uint(odd ? x1  : x0 );
            const uint32_t a1 = __float_as_uint(odd ? y1  : y0 );
            const uint32_t a2 = __float_as_uint(odd ? x1b : x0b);
            const uint32_t a3 = __float_as_uint(odd ? y1b : y0b);
            #pragma unroll
            for (int nt = 0; nt < 4; nt++) {
                const uint32_t b0 = __float_as_uint(Vb[s][kt * 8 + t    ][nt * 8 + g]);
                const uint32_t b1 = __float_as_uint(Vb[s][kt * 8 + t + 4][nt * 8 + g]);
                mma_tf32(of[nt], a0, a1, a2, a3, b0, b1);
            }
        }
        __syncthreads();
    }

    // ---- l reduce across t lanes ----
    l_lo += __shfl_xor_sync(0xffffffffu, l_lo, 1);
    l_lo += __shfl_xor_sync(0xffffffffu, l_lo, 2);
    l_hi += __shfl_xor_sync(0xffffffffu, l_hi, 1);
    l_hi += __shfl_xor_sync(0xffffffffu, l_hi, 2);

    const size_t r_lo = (size_t)b * Lq + q0 + 16 * w + g;
    const size_t r_hi = r_lo + 8;
    if (norm) {
        const float inv_lo = 1.0f / l_lo;
        const float inv_hi = 1.0f / l_hi;
        #pragma unroll
        for (int nt = 0; nt < 4; nt++) {
            const int col = h * 32 + nt * 8 + 2 * t;
            float2 lo, hi;
            lo.x = f2tf32f(of[nt][0] * inv_lo); lo.y = f2tf32f(of[nt][1] * inv_lo);
            hi.x = f2tf32f(of[nt][2] * inv_hi); hi.y = f2tf32f(of[nt][3] * inv_hi);
            *(float2*)&Op[r_lo * 256 + col] = lo;
            *(float2*)&Op[r_hi * 256 + col] = hi;
        }
    } else {
        #pragma unroll
        for (int nt = 0; nt < 4; nt++) {
            const int col = h * 32 + nt * 8 + 2 * t;
            *(float2*)&Op[r_lo * 256 + col] = make_float2(of[nt][0], of[nt][1]);
            *(float2*)&Op[r_hi * 256 + col] = make_float2(of[nt][2], of[nt][3]);
        }
        if (t == 0) {
            Lp[((size_t)b * HH + h) * Lq + q0 + 16 * w + g    ] = l_lo;
            Lp[((size_t)b * HH + h) * Lq + q0 + 16 * w + g + 8] = l_hi;
        }
    }
}

// ---------------------------------------------------------------------------
// Combine dir1 split partials: out = tf32((O0+O1)/(l0+l1))
// ---------------------------------------------------------------------------
__global__ void combine2(const float* __restrict__ po,
                         const float* __restrict__ pl,
                         float* __restrict__ out)
{
    const int i4 = (blockIdx.x * 256 + threadIdx.x) * 4;
    if (i4 >= BB * NN * DD) return;
    const int b = i4 / (NN * DD);
    const int rem = i4 - b * NN * DD;
    const int q = rem / DD;
    const int c = rem - q * DD;
    const int h = c >> 5;
    const float l = pl[((size_t)b * HH + h) * NN + q] +
                    pl[(size_t)BB * HH * NN + ((size_t)b * HH + h) * NN + q];
    const float inv = 1.0f / l;
    const float4 o0 = *(const float4*)&po[i4];
    const float4 o1 = *(const float4*)&po[BB * NN * DD + i4];
    float4 o;
    o.x = f2tf32f((o0.x + o1.x) * inv);
    o.y = f2tf32f((o0.y + o1.y) * inv);
    o.z = f2tf32f((o0.z + o1.z) * inv);
    o.w = f2tf32f((o0.w + o1.w) * inv);
    *(float4*)&out[i4] = o;
}

// ---------------------------------------------------------------------------
extern "C" void kernel_launch(void* const* d_in, const int* in_sizes, int n_in,
                              void* d_out, int out_size)
{
    const float* amr      = (const float*)d_in[0];
    const int*   pad_mask = (const int*)  d_in[1];
    const float* vis      = (const float*)d_in[2];
    const float* W_amr_qk = (const float*)d_in[3];
    const float* W_amr_v  = (const float*)d_in[4];
    const float* W_vis_qk = (const float*)d_in[5];
    const float* W_vis_v  = (const float*)d_in[6];
    const float* W_amr_out= (const float*)d_in[7];
    const float* b_amr_out= (const float*)d_in[8];
    const float* W_vis_out= (const float*)d_in[9];
    const float* b_vis_out= (const float*)d_in[10];

    float* out_amr = (float*)d_out;
    float* out_vis = out_amr + (size_t)BB * NN * DD;

    float *amr_t, *vis_t, *Wt, *amr_qk, *amr_v, *vis_qk, *vis_v;
    float *amr_att, *vis_att, *po, *pl;
    cudaGetSymbolAddress((void**)&amr_t,   g_amr_t);
    cudaGetSymbolAddress((void**)&vis_t,   g_vis_t);
    cudaGetSymbolAddress((void**)&Wt,      g_Wt);
    cudaGetSymbolAddress((void**)&amr_qk,  g_amr_qk);
    cudaGetSymbolAddress((void**)&amr_v,   g_amr_v);
    cudaGetSymbolAddress((void**)&vis_qk,  g_vis_qk);
    cudaGetSymbolAddress((void**)&vis_v,   g_vis_v);
    cudaGetSymbolAddress((void**)&amr_att, g_amr_att);
    cudaGetSymbolAddress((void**)&vis_att, g_vis_att);
    cudaGetSymbolAddress((void**)&po,      g_po);
    cudaGetSymbolAddress((void**)&pl,      g_pl);

    // --- Prep: round inputs, transpose+round weights ---
    round_tf32<<<(BB*NN*DD)/1024, 256>>>(amr, amr_t, BB*NN*DD);
    round_tf32<<<(BB*MM*DD)/1024, 256>>>(vis, vis_t, BB*MM*DD);
    transpose_w<<<dim3(8, 8, 6), dim3(32, 8)>>>(W_amr_qk, W_amr_v, W_vis_qk,
                                                W_vis_v, W_amr_out, W_vis_out, Wt);

    const dim3 gA(4, (BB * NN) / 64);
    const dim3 gV(4, (BB * MM) / 64);

    // --- Projections ---
    gemm2<false><<<gA, 128>>>(amr_t, Wt + 0*DD*DD, nullptr, nullptr, amr_qk);
    gemm2<false><<<gA, 128>>>(amr_t, Wt + 1*DD*DD, nullptr, nullptr, amr_v);
    gemm2<false><<<gV, 128>>>(vis_t, Wt + 2*DD*DD, nullptr, nullptr, vis_qk);
    gemm2<false><<<gV, 128>>>(vis_t, Wt + 3*DD*DD, nullptr, nullptr, vis_v);

    // --- Dir 1: amr -> visual, split-KV x2 (unnormalized partials) ---
    attn2<<<dim3(NN/64, HH, BB), 128>>>(amr_qk, vis_qk, vis_v,
                                        po,                    pl,
                                        nullptr, NN, MM, 0,    MM/2, 0);
    attn2<<<dim3(NN/64, HH, BB), 128>>>(amr_qk, vis_qk, vis_v,
                                        po + (size_t)BB*NN*DD, pl + BB*HH*NN,
                                        nullptr, NN, MM, MM/2, MM/2, 0);
    combine2<<<(BB*NN*DD)/1024, 256>>>(po, pl, amr_att);

    // --- Dir 2: visual -> amr, masked keys, single pass normalized ---
    attn2<<<dim3(MM/64, HH, BB), 128>>>(vis_qk, amr_qk, amr_v,
                                        vis_att, nullptr,
                                        pad_mask, MM, NN, 0, NN, 1);

    // --- Output projections with fused bias + gate (raw-precision gate) ---
    gemm2<true><<<gA, 128>>>(amr_att, Wt + 4*DD*DD, b_amr_out, amr, out_amr);
    gemm2<true><<<gV, 128>>>(vis_att, Wt + 5*DD*DD, b_vis_out, vis, out_vis);
}

// round 8
// speedup vs baseline: 6.5332x; 1.7439x over previous
#include <cuda_runtime.h>
#include <cuda_fp16.h>
#include <stdint.h>

// Problem constants
#define BB 4
#define NN 512
#define MM 4096
#define DD 256
#define HH 8
#define C2EXP 0.25505551190558915f   // (1/sqrt(32)) * log2(e)

// ---------------------------------------------------------------------------
// Scratch (static device globals)
// ---------------------------------------------------------------------------
__device__ __half g_amr_h [BB*NN*DD];
__device__ __half g_vis_h [BB*MM*DD];
__device__ __half g_Wt    [6*DD*DD];          // transposed weights [n][k] f16
__device__ __half g_amr_qk[BB*NN*DD];
__device__ __half g_amr_v [BB*NN*DD];
__device__ __half g_vis_qk[BB*MM*DD];
__device__ __half g_vis_v [BB*MM*DD];
__device__ __half g_amr_att[BB*NN*DD];
__device__ __half g_vis_att[BB*MM*DD];
__device__ float  g_po[2*BB*NN*DD];           // dir1 split partial O
__device__ float  g_pl[2*BB*HH*NN];           // dir1 split partial l

// ---------------------------------------------------------------------------
// Helpers
// ---------------------------------------------------------------------------
__device__ __forceinline__ void mma_f16(float c[4],
                                        uint32_t a0, uint32_t a1,
                                        uint32_t a2, uint32_t a3,
                                        uint32_t b0, uint32_t b1) {
    asm volatile(
        "mma.sync.aligned.m16n8k16.row.col.f32.f16.f16.f32 "
        "{%0,%1,%2,%3}, {%4,%5,%6,%7}, {%8,%9}, {%0,%1,%2,%3};"
        : "+f"(c[0]), "+f"(c[1]), "+f"(c[2]), "+f"(c[3])
        : "r"(a0), "r"(a1), "r"(a2), "r"(a3), "r"(b0), "r"(b1));
}

__device__ __forceinline__ uint32_t smem_u32(const void* p) {
    return (uint32_t)__cvta_generic_to_shared(p);
}

#define CP16(dst_u32, src) \
    asm volatile("cp.async.ca.shared.global [%0], [%1], 16;" \
                 :: "r"(dst_u32), "l"(src))
#define CP_COMMIT() asm volatile("cp.async.commit_group;")
#define CP_WAIT(n)  asm volatile("cp.async.wait_group %0;" :: "n"(n))

#define LDM4(r0, r1, r2, r3, addr) \
    asm volatile("ldmatrix.sync.aligned.m8n8.x4.shared.b16 {%0,%1,%2,%3}, [%4];" \
                 : "=r"(r0), "=r"(r1), "=r"(r2), "=r"(r3) : "r"(addr))
#define LDM4T(r0, r1, r2, r3, addr) \
    asm volatile("ldmatrix.sync.aligned.m8n8.x4.trans.shared.b16 {%0,%1,%2,%3}, [%4];" \
                 : "=r"(r0), "=r"(r1), "=r"(r2), "=r"(r3) : "r"(addr))

// pack two f32 -> f16x2 (lo = a, hi = b)
__device__ __forceinline__ uint32_t pack_h2(float a, float b) {
    uint32_t r;
    asm("cvt.rn.f16x2.f32 %0, %1, %2;" : "=r"(r) : "f"(b), "f"(a));
    return r;
}
__device__ __forceinline__ uint32_t ex2_h2(uint32_t x) {
    uint32_t r;
    asm("ex2.approx.f16x2 %0, %1;" : "=r"(r) : "r"(x));
    return r;
}

// ---------------------------------------------------------------------------
// Prep: fp32 -> fp16 for both feature arrays in one launch
// ---------------------------------------------------------------------------
__global__ void to_half(const float* __restrict__ amr, const float* __restrict__ vis,
                        __half* __restrict__ amr_h, __half* __restrict__ vis_h)
{
    int i4 = (blockIdx.x * 256 + threadIdx.x) * 4;
    const int na = BB * NN * DD;
    const float* src; __half* dst;
    if (i4 < na) { src = amr; dst = amr_h; }
    else {
        i4 -= na;
        if (i4 >= BB * MM * DD) return;
        src = vis; dst = vis_h;
    }
    const float4 v = *(const float4*)&src[i4];
    *(half2*)&dst[i4]     = __floats2half2_rn(v.x, v.y);
    *(half2*)&dst[i4 + 2] = __floats2half2_rn(v.z, v.w);
}

// Prep: transpose 6 weight matrices to f16 [n][k]
__global__ void transpose_w(const float* W0, const float* W1, const float* W2,
                            const float* W3, const float* W4, const float* W5,
                            __half* __restrict__ Wt)
{
    __shared__ float tile[32][33];
    const float* Ws[6] = {W0, W1, W2, W3, W4, W5};
    const float* in = Ws[blockIdx.z];
    __half* out = Wt + (size_t)blockIdx.z * DD * DD;
    const int x0 = blockIdx.x * 32;      // n
    const int y0 = blockIdx.y * 32;      // k
    const int tx = threadIdx.x, ty = threadIdx.y;
    #pragma unroll
    for (int j = 0; j < 32; j += 8)
        tile[ty + j][tx] = in[(size_t)(y0 + ty + j) * DD + x0 + tx];
    __syncthreads();
    #pragma unroll
    for (int j = 0; j < 32; j += 8)
        out[(size_t)(x0 + ty + j) * DD + y0 + tx] = __float2half(tile[tx][ty + j]);
}

// ---------------------------------------------------------------------------
// fp16 GEMM body: C[64x64 tile] = A[S,256] @ Wt[n][k]^T, fp32 accum.
// 128 threads / 4 warps. k-chunks of 64, 2-stage cp.async.
// EPI=false: C -> half. EPI=true: C = (acc + bias) * Xm -> float.
// ---------------------------------------------------------------------------
template <bool EPI>
__device__ __forceinline__ void gemm_body(const __half* __restrict__ A,
                                          const __half* __restrict__ W,
                                          const float* __restrict__ bias,
                                          const float* __restrict__ Xm,
                                          __half* __restrict__ Ch,
                                          float* __restrict__ Cf,
                                          int row0, int col0)
{
    __shared__ __half Ab[2][64][72];
    __shared__ __half Wb[2][64][72];

    const int tid  = threadIdx.x;
    const int w    = tid >> 5;
    const int lane = tid & 31;
    const int g    = lane >> 2;
    const int t    = lane & 3;
    const int m    = lane >> 3;
    const int r    = lane & 7;
    const int sr   = tid >> 1;            // staging row
    const int scb  = (tid & 1) * 32;      // staging col base (halves)

    const uint32_t abase = smem_u32(&Ab[0][0][0]);
    const uint32_t wbase = smem_u32(&Wb[0][0][0]);
    const uint32_t BUF = 64 * 72 * 2;     // 9216 bytes
    const uint32_t a_l = (uint32_t)(((m & 1) * 8 + r) * 144 + (m >> 1) * 16);
    const uint32_t w_l = (uint32_t)(((m >> 1) * 8 + r) * 144 + (m & 1) * 16);

    float acc[8][4];
    #pragma unroll
    for (int nt = 0; nt < 8; nt++)
        #pragma unroll
        for (int i = 0; i < 4; i++) acc[nt][i] = 0.0f;

    auto stage = [&](int s, int kc) {
        const __half* ap = &A[(size_t)(row0 + sr) * 256 + kc + scb];
        const __half* wp = &W[(size_t)(col0 + sr) * 256 + kc + scb];
        #pragma unroll
        for (int o = 0; o < 32; o += 8) {
            CP16(smem_u32(&Ab[s][sr][scb + o]), ap + o);
            CP16(smem_u32(&Wb[s][sr][scb + o]), wp + o);
        }
    };

    stage(0, 0); CP_COMMIT();

    for (int c = 0; c < 4; c++) {
        if (c < 3) { stage((c + 1) & 1, (c + 1) * 64); CP_COMMIT(); CP_WAIT(1); }
        else       { CP_WAIT(0); }
        __syncthreads();
        const int s = c & 1;
        const uint32_t ab = abase + s * BUF + w * 2304 + a_l;
        const uint32_t wb = wbase + s * BUF + w_l;
        #pragma unroll
        for (int kk = 0; kk < 4; kk++) {
            uint32_t a0, a1, a2, a3;
            LDM4(a0, a1, a2, a3, ab + kk * 32);
            #pragma unroll
            for (int j = 0; j < 4; j++) {
                uint32_t b00, b01, b10, b11;
                LDM4(b00, b01, b10, b11, wb + j * 2304 + kk * 32);
                mma_f16(acc[2 * j],     a0, a1, a2, a3, b00, b01);
                mma_f16(acc[2 * j + 1], a0, a1, a2, a3, b10, b11);
            }
        }
        __syncthreads();
    }

    const size_t r_lo = (size_t)(row0 + 16 * w + g);
    const size_t r_hi = r_lo + 8;
    #pragma unroll
    for (int nt = 0; nt < 8; nt++) {
        const int col = col0 + nt * 8 + 2 * t;
        if (EPI) {
            const float2 bv  = *(const float2*)&bias[col];
            const float2 xlo = *(const float2*)&Xm[r_lo * 256 + col];
            const float2 xhi = *(const float2*)&Xm[r_hi * 256 + col];
            float2 lo, hi;
            lo.x = (acc[nt][0] + bv.x) * xlo.x; lo.y = (acc[nt][1] + bv.y) * xlo.y;
            hi.x = (acc[nt][2] + bv.x) * xhi.x; hi.y = (acc[nt][3] + bv.y) * xhi.y;
            *(float2*)&Cf[r_lo * 256 + col] = lo;
            *(float2*)&Cf[r_hi * 256 + col] = hi;
        } else {
            *(half2*)&Ch[r_lo * 256 + col] = __floats2half2_rn(acc[nt][0], acc[nt][1]);
            *(half2*)&Ch[r_hi * 256 + col] = __floats2half2_rn(acc[nt][2], acc[nt][3]);
        }
    }
}

// All 4 projections in one launch: grid (4, 576)
__global__ void __launch_bounds__(128) proj_all(const __half* amr_h, const __half* vis_h,
                                                const __half* Wt,
                                                __half* amr_qk, __half* amr_v,
                                                __half* vis_qk, __half* vis_v)
{
    const int y = blockIdx.y;
    const int col0 = blockIdx.x * 64;
    const __half *A, *W; __half* C; int row0;
    if      (y < 32)  { A = amr_h; W = Wt + 0 * DD * DD; C = amr_qk; row0 = y * 64; }
    else if (y < 64)  { A = amr_h; W = Wt + 1 * DD * DD; C = amr_v;  row0 = (y - 32) * 64; }
    else if (y < 320) { A = vis_h; W = Wt + 2 * DD * DD; C = vis_qk; row0 = (y - 64) * 64; }
    else              { A = vis_h; W = Wt + 3 * DD * DD; C = vis_v;  row0 = (y - 320) * 64; }
    gemm_body<false>(A, W, nullptr, nullptr, C, nullptr, row0, col0);
}

// Both epilogue GEMMs in one launch: grid (4, 288)
__global__ void __launch_bounds__(128) epi_all(const __half* amr_att, const __half* vis_att,
                                               const __half* Wt,
                                               const float* b_amr, const float* b_vis,
                                               const float* amr_f, const float* vis_f,
                                               float* out_amr, float* out_vis)
{
    const int y = blockIdx.y;
    const int col0 = blockIdx.x * 64;
    const __half *A, *W; const float *bias, *Xm; float* C; int row0;
    if (y < 32) { A = amr_att; W = Wt + 4 * DD * DD; bias = b_amr; Xm = amr_f;
                  C = out_amr; row0 = y * 64; }
    else        { A = vis_att; W = Wt + 5 * DD * DD; bias = b_vis; Xm = vis_f;
                  C = out_vis; row0 = (y - 32) * 64; }
    gemm_body<true>(A, W, bias, Xm, nullptr, C, row0, col0);
}

// ---------------------------------------------------------------------------
// Fused attention, fp16 mma, fp32 accum, exp2 in f16x2, l via ones-mma.
// Grid 2560 1D: [0,512) dir1 (amr->vis, split-KV x2, unnormalized partials),
//               [512,2560) dir2 (vis->amr, masked keys, normalized).
// 128 threads / 4 warps; 64 queries/block; 64-key chunks, 2-stage cp.async.
// ---------------------------------------------------------------------------
__global__ void __launch_bounds__(128) attn_all(
    const __half* __restrict__ amr_qk, const __half* __restrict__ amr_v,
    const __half* __restrict__ vis_qk, const __half* __restrict__ vis_v,
    __half* __restrict__ vis_att, float* __restrict__ po, float* __restrict__ pl,
    const int* __restrict__ pad_mask)
{
    __shared__ __half Qs[64][40];
    __shared__ __half Kb[2][64][40];
    __shared__ __half Vb[2][64][40];
    __shared__ int    Msk[2][64];

    // --- decode block role ---
    const __half *Qp, *Kp, *Vp;
    int Lq, LkT, kv0, nch, b, h, q0, norm;
    const int* mask;
    float* Opf = nullptr; float* Lp = nullptr; __half* Oph = nullptr;
    {
        const int id = blockIdx.x;
        if (id < 512) {
            b = id & 3; h = (id >> 2) & 7; q0 = ((id >> 5) & 7) * 64;
            const int sp = id >> 8;
            Qp = amr_qk; Kp = vis_qk; Vp = vis_v;
            Lq = NN; LkT = MM; kv0 = sp * (MM / 2); nch = (MM / 2) / 64;
            mask = nullptr; norm = 0;
            Opf = po + (size_t)sp * BB * NN * DD;
            Lp  = pl + sp * BB * HH * NN;
        } else {
            const int j = id - 512;
            b = j & 3; h = (j >> 2) & 7; q0 = (j >> 5) * 64;
            Qp = vis_qk; Kp = amr_qk; Vp = amr_v;
            Lq = MM; LkT = NN; kv0 = 0; nch = NN / 64;
            mask = pad_mask; norm = 1;
            Oph = vis_att;
        }
    }

    const int tid  = threadIdx.x;
    const int w    = tid >> 5;
    const int lane = tid & 31;
    const int g    = lane >> 2;
    const int t    = lane & 3;
    const int m    = lane >> 3;
    const int r    = lane & 7;
    const int sr   = tid >> 1;
    const int scb  = (tid & 1) * 16;

    const uint32_t qbase = smem_u32(&Qs[0][0]);
    const uint32_t kbase = smem_u32(&Kb[0][0][0]);
    const uint32_t vbase = smem_u32(&Vb[0][0][0]);
    const uint32_t KBUF = 64 * 40 * 2;    // 5120 bytes
    const uint32_t q_l = (uint32_t)(((m & 1) * 8 + r) * 80 + (m >> 1) * 16);
    const uint32_t k_l = (uint32_t)(((m >> 1) * 8 + r) * 80 + (m & 1) * 16);
    const uint32_t v_l = (uint32_t)(r * 80 + m * 16);
    const uint32_t onesb = (g == 0) ? 0x3C003C00u : 0u;   // {1,1} f16x2 on g==0

    auto stageKV = [&](int s, int kc) {
        const size_t base = ((size_t)b * LkT + kv0 + kc + sr) * 256 + h * 32 + scb;
        CP16(smem_u32(&Kb[s][sr][scb]),     &Kp[base]);
        CP16(smem_u32(&Kb[s][sr][scb + 8]), &Kp[base + 8]);
        CP16(smem_u32(&Vb[s][sr][scb]),     &Vp[base]);
        CP16(smem_u32(&Vb[s][sr][scb + 8]), &Vp[base + 8]);
        if (mask && tid < 16)
            CP16(smem_u32(&Msk[s][tid * 4]), &mask[b * LkT + kv0 + kc + tid * 4]);
    };

    // Stage Q + first KV chunk in group 0
    {
        const size_t qb = ((size_t)b * Lq + q0 + sr) * 256 + h * 32 + scb;
        CP16(smem_u32(&Qs[sr][scb]),     &Qp[qb]);
        CP16(smem_u32(&Qs[sr][scb + 8]), &Qp[qb + 8]);
    }
    stageKV(0, 0);
    CP_COMMIT();

    uint32_t qa[2][4];
    float of[4][4], lf[4];
    #pragma unroll
    for (int nt = 0; nt < 4; nt++)
        #pragma unroll
        for (int i = 0; i < 4; i++) of[nt][i] = 0.0f;
    #pragma unroll
    for (int i = 0; i < 4; i++) lf[i] = 0.0f;

    for (int c = 0; c < nch; c++) {
        if (c + 1 < nch) { stageKV((c + 1) & 1, (c + 1) * 64); CP_COMMIT(); CP_WAIT(1); }
        else             { CP_WAIT(0); }
        __syncthreads();
        const int s = c & 1;

        if (c == 0) {
            const uint32_t qb = qbase + w * 1280 + q_l;
            LDM4(qa[0][0], qa[0][1], qa[0][2], qa[0][3], qb);
            LDM4(qa[1][0], qa[1][1], qa[1][2], qa[1][3], qb + 32);
        }

        // ---- Scores: S (16x64 per warp) = Q K^T ----
        float sf[8][4];
        #pragma unroll
        for (int nt = 0; nt < 8; nt++) {
            sf[nt][0] = 0.0f; sf[nt][1] = 0.0f; sf[nt][2] = 0.0f; sf[nt][3] = 0.0f;
        }
        {
            const uint32_t kb = kbase + s * KBUF + k_l;
            #pragma unroll
            for (int j = 0; j < 4; j++) {
                #pragma unroll
                for (int kk = 0; kk < 2; kk++) {
                    uint32_t b00, b01, b10, b11;
                    LDM4(b00, b01, b10, b11, kb + j * 1280 + kk * 32);
                    mma_f16(sf[2 * j],     qa[kk][0], qa[kk][1], qa[kk][2], qa[kk][3], b00, b01);
                    mma_f16(sf[2 * j + 1], qa[kk][0], qa[kk][1], qa[kk][2], qa[kk][3], b10, b11);
                }
            }
        }

        // ---- mask, exp2 (f16x2), P fragments (no shuffles) ----
        uint32_t pl2[8], ph2[8];
        #pragma unroll
        for (int nt = 0; nt < 8; nt++) {
            if (mask) {
                const int cb = nt * 8 + 2 * t;
                if (Msk[s][cb    ]) { sf[nt][0] = -3.0e38f; sf[nt][2] = -3.0e38f; }
                if (Msk[s][cb + 1]) { sf[nt][1] = -3.0e38f; sf[nt][3] = -3.0e38f; }
            }
            pl2[nt] = ex2_h2(pack_h2(sf[nt][0] * C2EXP, sf[nt][1] * C2EXP));
            ph2[nt] = ex2_h2(pack_h2(sf[nt][2] * C2EXP, sf[nt][3] * C2EXP));
        }

        // ---- PV: O (16x32) += P (16x64) @ V (64x32); l via ones column ----
        {
            const uint32_t vb = vbase + s * KBUF + v_l;
            #pragma unroll
            for (int kt = 0; kt < 4; kt++) {
                uint32_t b0[4], b1[4];
                LDM4T(b0[0], b0[1], b0[2], b0[3], vb + kt * 1280);
                LDM4T(b1[0], b1[1], b1[2], b1[3], vb + kt * 1280 + 640);
                const uint32_t a0 = pl2[2 * kt], a1 = ph2[2 * kt];
                const uint32_t a2 = pl2[2 * kt + 1], a3 = ph2[2 * kt + 1];
                #pragma unroll
                for (int nt = 0; nt < 4; nt++)
                    mma_f16(of[nt], a0, a1, a2, a3, b0[nt], b1[nt]);
                mma_f16(lf, a0, a1, a2, a3, onesb, onesb);
            }
        }
        __syncthreads();
    }

    // l lives at t==0 lanes (col 0 of the l-tile); broadcast within group
    const float l_lo = __shfl_sync(0xffffffffu, lf[0], lane & 28);
    const float l_hi = __shfl_sync(0xffffffffu, lf[2], lane & 28);

    const size_t r_lo = (size_t)b * Lq + q0 + 16 * w + g;
    const size_t r_hi = r_lo + 8;
    if (norm) {
        const float inv_lo = 1.0f / l_lo;
        const float inv_hi = 1.0f / l_hi;
        #pragma unroll
        for (int nt = 0; nt < 4; nt++) {
            const int col = h * 32 + nt * 8 + 2 * t;
            *(half2*)&Oph[r_lo * 256 + col] =
                __floats2half2_rn(of[nt][0] * inv_lo, of[nt][1] * inv_lo);
            *(half2*)&Oph[r_hi * 256 + col] =
                __floats2half2_rn(of[nt][2] * inv_hi, of[nt][3] * inv_hi);
        }
    } else {
        #pragma unroll
        for (int nt = 0; nt < 4; nt++) {
            const int col = h * 32 + nt * 8 + 2 * t;
            *(float2*)&Opf[r_lo * 256 + col] = make_float2(of[nt][0], of[nt][1]);
            *(float2*)&Opf[r_hi * 256 + col] = make_float2(of[nt][2], of[nt][3]);
        }
        if (t == 0) {
            Lp[((size_t)b * HH + h) * NN + q0 + 16 * w + g    ] = lf[0];
            Lp[((size_t)b * HH + h) * NN + q0 + 16 * w + g + 8] = lf[2];
        }
    }
}

// ---------------------------------------------------------------------------
// Combine dir1 split partials: att = f16((O0+O1)/(l0+l1))
// ---------------------------------------------------------------------------
__global__ void combine2(const float* __restrict__ po,
                         const float* __restrict__ pl,
                         __half* __restrict__ out)
{
    const int i4 = (blockIdx.x * 256 + threadIdx.x) * 4;
    if (i4 >= BB * NN * DD) return;
    const int b = i4 / (NN * DD);
    const int rem = i4 - b * NN * DD;
    const int q = rem / DD;
    const int c = rem - q * DD;
    const int h = c >> 5;
    const float l = pl[((size_t)b * HH + h) * NN + q] +
                    pl[(size_t)BB * HH * NN + ((size_t)b * HH + h) * NN + q];
    const float inv = 1.0f / l;
    const float4 o0 = *(const float4*)&po[i4];
    const float4 o1 = *(const float4*)&po[BB * NN * DD + i4];
    *(half2*)&out[i4]     = __floats2half2_rn((o0.x + o1.x) * inv, (o0.y + o1.y) * inv);
    *(half2*)&out[i4 + 2] = __floats2half2_rn((o0.z + o1.z) * inv, (o0.w + o1.w) * inv);
}

// ---------------------------------------------------------------------------
extern "C" void kernel_launch(void* const* d_in, const int* in_sizes, int n_in,
                              void* d_out, int out_size)
{
    const float* amr      = (const float*)d_in[0];
    const int*   pad_mask = (const int*)  d_in[1];
    const float* vis      = (const float*)d_in[2];
    const float* W_amr_qk = (const float*)d_in[3];
    const float* W_amr_v  = (const float*)d_in[4];
    const float* W_vis_qk = (const float*)d_in[5];
    const float* W_vis_v  = (const float*)d_in[6];
    const float* W_amr_out= (const float*)d_in[7];
    const float* b_amr_out= (const float*)d_in[8];
    const float* W_vis_out= (const float*)d_in[9];
    const float* b_vis_out= (const float*)d_in[10];

    float* out_amr = (float*)d_out;
    float* out_vis = out_amr + (size_t)BB * NN * DD;

    __half *amr_h, *vis_h, *Wt, *amr_qk, *amr_v, *vis_qk, *vis_v, *amr_att, *vis_att;
    float *po, *pl;
    cudaGetSymbolAddress((void**)&amr_h,   g_amr_h);
    cudaGetSymbolAddress((void**)&vis_h,   g_vis_h);
    cudaGetSymbolAddress((void**)&Wt,      g_Wt);
    cudaGetSymbolAddress((void**)&amr_qk,  g_amr_qk);
    cudaGetSymbolAddress((void**)&amr_v,   g_amr_v);
    cudaGetSymbolAddress((void**)&vis_qk,  g_vis_qk);
    cudaGetSymbolAddress((void**)&vis_v,   g_vis_v);
    cudaGetSymbolAddress((void**)&amr_att, g_amr_att);
    cudaGetSymbolAddress((void**)&vis_att, g_vis_att);
    cudaGetSymbolAddress((void**)&po,      g_po);
    cudaGetSymbolAddress((void**)&pl,      g_pl);

    // Prep
    to_half<<<(BB*NN*DD + BB*MM*DD) / 1024, 256>>>(amr, vis, amr_h, vis_h);
    transpose_w<<<dim3(8, 8, 6), dim3(32, 8)>>>(W_amr_qk, W_amr_v, W_vis_qk,
                                                W_vis_v, W_amr_out, W_vis_out, Wt);

    // All 4 projections, one launch
    proj_all<<<dim3(4, 576), 128>>>(amr_h, vis_h, Wt, amr_qk, amr_v, vis_qk, vis_v);

    // Both attention directions, one launch (dir1 split x2 || dir2)
    attn_all<<<2560, 128>>>(amr_qk, amr_v, vis_qk, vis_v, vis_att, po, pl, pad_mask);

    // Combine dir1 partials
    combine2<<<(BB*NN*DD) / 1024, 256>>>(po, pl, amr_att);

    // Both output projections (+bias, *gate), one launch
    epi_all<<<dim3(4, 288), 128>>>(amr_att, vis_att, Wt, b_amr_out, b_vis_out,
                                   amr, vis, out_amr, out_vis);
}